// round 3
// baseline (speedup 1.0000x reference)
#include <cuda_runtime.h>
#include <cstdint>

#define N_NODES 100000
#define N_EDGES 640000
#define IN_CH 128
#define HID 128
#define OUT_CH 64

// ---------------- scratch (device globals; no allocation allowed) ----------
__device__ float g_agg1[N_NODES * IN_CH];        // sum of x[src] at dst
__device__ float g_h[N_NODES * HID];             // layer-1 output
__device__ float g_t2[N_NODES * (2 * OUT_CH)];   // [h@W2_l | h@W2_r]
__device__ float g_agg2[N_NODES * OUT_CH];       // sum of t2[src,0:64] at dst
__device__ float g_cnt[N_NODES];                 // in-degree (float)
__device__ float g_W1[2 * IN_CH * HID];          // [W1_l; W1_r]  (256 x 128)
__device__ float g_W2[HID * 2 * OUT_CH];         // [W2_l | W2_r] (128 x 128)

// ---------------- weight concatenation ------------------------------------
__global__ void prep_weights(const float* __restrict__ W1l,
                             const float* __restrict__ W1r,
                             const float* __restrict__ W2l,
                             const float* __restrict__ W2r,
                             float* __restrict__ W1c,
                             float* __restrict__ W2c) {
    int t = blockIdx.x * blockDim.x + threadIdx.x;   // 0 .. 16383
    if (t < IN_CH * HID) {
        W1c[t] = W1l[t];
        W1c[IN_CH * HID + t] = W1r[t];
    }
    if (t < HID * 2 * OUT_CH) {
        int k = t >> 7;          // row (k index)
        int n = t & 127;         // col
        W2c[t] = (n < OUT_CH) ? W2l[k * OUT_CH + n]
                              : W2r[k * OUT_CH + (n - OUT_CH)];
    }
}

// ---------------- edge scatter (float4 gather, scalar RED) ------------------
// thread t handles float4 #j of edge e.  SRCD4/DSTD4 = row widths in float4s.
// Edge indices are int32 (harness converts int64 -> int32). Clamped for safety.
template<int SRCD4, int DSTD4, bool COUNT>
__global__ void scatter_kernel(const float* __restrict__ feat,
                               const int* __restrict__ ei,
                               float* __restrict__ agg,
                               float* __restrict__ cnt) {
    long long t = (long long)blockIdx.x * blockDim.x + threadIdx.x;
    if (t >= (long long)N_EDGES * DSTD4) return;
    int e = (int)(t / DSTD4);
    int j = (int)(t % DSTD4);
    int s = ei[e];
    int d = ei[N_EDGES + e];
    s = min(max(s, 0), N_NODES - 1);
    d = min(max(d, 0), N_NODES - 1);
    float4 v = ((const float4*)feat)[(long long)s * SRCD4 + j];
    float* p = agg + ((long long)d * DSTD4 + j) * 4;
    atomicAdd(p + 0, v.x);
    atomicAdd(p + 1, v.y);
    atomicAdd(p + 2, v.z);
    atomicAdd(p + 3, v.w);
    if (COUNT && j == 0) atomicAdd(cnt + d, 1.0f);
}

// ---------------- SGEMM: C[M x 128] = A[M x K] * B[K x 128] ----------------
// BM=128, BN=128, BK=16; 256 threads, 8x8 microtile per thread.
// FUSED: A is [A0*diag(1/cnt) | A1] with K = KT*16 split evenly.
// RELUBIAS: epilogue adds bias and applies relu.
template<int KT, bool FUSED, bool RELUBIAS>
__global__ void __launch_bounds__(256, 2)
sgemm_k(const float* __restrict__ A0, const float* __restrict__ A1,
        const float* __restrict__ cntp, const float* __restrict__ B,
        const float* __restrict__ bias, float* __restrict__ C) {
    __shared__ float As[16][128];
    __shared__ float Bs[16][128];

    const int tid = threadIdx.x;
    const int r   = tid >> 1;          // 0..127 : row within tile this thread loads
    const int cc  = (tid & 1) << 3;    // 0 or 8 : k-offset this thread loads
    const long long gr = (long long)blockIdx.x * 128 + r;
    const bool rowok = gr < N_NODES;

    float scale = 1.f;
    if (FUSED) scale = rowok ? (1.f / fmaxf(cntp[gr], 1.f)) : 0.f;

    const int ty = tid >> 4;           // 0..15
    const int tx = tid & 15;           // 0..15

    float acc[8][8];
#pragma unroll
    for (int i = 0; i < 8; i++)
#pragma unroll
        for (int j = 0; j < 8; j++) acc[i][j] = 0.f;

    for (int kt = 0; kt < KT; ++kt) {
        const float* Asrc;
        int kcol;
        float s;
        if (FUSED && kt >= KT / 2) {
            Asrc = A1; kcol = (kt - KT / 2) * 16; s = 1.f;
        } else {
            Asrc = A0; kcol = kt * 16; s = FUSED ? scale : 1.f;
        }
        float4 a0 = make_float4(0.f, 0.f, 0.f, 0.f), a1 = a0;
        if (rowok) {
            const float* p = Asrc + gr * 128 + kcol + cc;
            a0 = *(const float4*)p;
            a1 = *(const float4*)(p + 4);
        }
        As[cc + 0][r] = a0.x * s; As[cc + 1][r] = a0.y * s;
        As[cc + 2][r] = a0.z * s; As[cc + 3][r] = a0.w * s;
        As[cc + 4][r] = a1.x * s; As[cc + 5][r] = a1.y * s;
        As[cc + 6][r] = a1.z * s; As[cc + 7][r] = a1.w * s;
        {
            const float4* Bp = (const float4*)(B + (long long)kt * 16 * 128);
            float4* Bs4 = (float4*)Bs;
            Bs4[tid]       = Bp[tid];
            Bs4[tid + 256] = Bp[tid + 256];
        }
        __syncthreads();
#pragma unroll
        for (int k = 0; k < 16; k++) {
            float4 av0 = *(const float4*)&As[k][ty * 8];
            float4 av1 = *(const float4*)&As[k][ty * 8 + 4];
            float4 bv0 = *(const float4*)&Bs[k][tx * 8];
            float4 bv1 = *(const float4*)&Bs[k][tx * 8 + 4];
            float a[8] = {av0.x, av0.y, av0.z, av0.w, av1.x, av1.y, av1.z, av1.w};
            float b[8] = {bv0.x, bv0.y, bv0.z, bv0.w, bv1.x, bv1.y, bv1.z, bv1.w};
#pragma unroll
            for (int i = 0; i < 8; i++)
#pragma unroll
                for (int j = 0; j < 8; j++)
                    acc[i][j] = fmaf(a[i], b[j], acc[i][j]);
        }
        __syncthreads();
    }

    float bb[8];
    if (RELUBIAS) {
#pragma unroll
        for (int j = 0; j < 8; j++) bb[j] = bias[tx * 8 + j];
    }
#pragma unroll
    for (int i = 0; i < 8; i++) {
        long long row = (long long)blockIdx.x * 128 + ty * 8 + i;
        if (row >= N_NODES) continue;
        float v[8];
#pragma unroll
        for (int j = 0; j < 8; j++) {
            float val = acc[i][j];
            if (RELUBIAS) val = fmaxf(val + bb[j], 0.f);
            v[j] = val;
        }
        float* cp = C + row * 128 + tx * 8;
        *(float4*)cp       = make_float4(v[0], v[1], v[2], v[3]);
        *(float4*)(cp + 4) = make_float4(v[4], v[5], v[6], v[7]);
    }
}

// ---------------- finalize: out = agg2/cnt + t2[:,64:] + b2 ----------------
__global__ void finalize_kernel(const float* __restrict__ agg2,
                                const float* __restrict__ t2,
                                const float* __restrict__ cnt,
                                const float* __restrict__ b2,
                                float* __restrict__ out) {
    int t = blockIdx.x * blockDim.x + threadIdx.x;   // per float4
    if (t >= N_NODES * 16) return;
    int i = t >> 4;
    int j = t & 15;
    float inv = 1.f / fmaxf(cnt[i], 1.f);
    float4 a  = ((const float4*)agg2)[t];
    float4 tv = ((const float4*)t2)[(long long)i * 32 + 16 + j];
    float4 b  = ((const float4*)b2)[j];
    float4 o;
    o.x = fmaf(a.x, inv, tv.x + b.x);
    o.y = fmaf(a.y, inv, tv.y + b.y);
    o.z = fmaf(a.z, inv, tv.z + b.z);
    o.w = fmaf(a.w, inv, tv.w + b.w);
    ((float4*)out)[t] = o;
}

// ---------------- launch ----------------------------------------------------
extern "C" void kernel_launch(void* const* d_in, const int* in_sizes, int n_in,
                              void* d_out, int out_size) {
    const float* x   = (const float*)d_in[0];
    const int*   ei  = (const int*)d_in[1];
    const float* W1l = (const float*)d_in[2];
    const float* W1r = (const float*)d_in[3];
    const float* b1  = (const float*)d_in[4];
    const float* W2l = (const float*)d_in[5];
    const float* W2r = (const float*)d_in[6];
    const float* b2  = (const float*)d_in[7];
    float* out = (float*)d_out;

    float *agg1, *agg2, *cnt, *h, *t2, *W1c, *W2c;
    cudaGetSymbolAddress((void**)&agg1, g_agg1);
    cudaGetSymbolAddress((void**)&agg2, g_agg2);
    cudaGetSymbolAddress((void**)&cnt,  g_cnt);
    cudaGetSymbolAddress((void**)&h,    g_h);
    cudaGetSymbolAddress((void**)&t2,   g_t2);
    cudaGetSymbolAddress((void**)&W1c,  g_W1);
    cudaGetSymbolAddress((void**)&W2c,  g_W2);

    cudaMemsetAsync(agg1, 0, sizeof(float) * N_NODES * IN_CH, 0);
    cudaMemsetAsync(agg2, 0, sizeof(float) * N_NODES * OUT_CH, 0);
    cudaMemsetAsync(cnt,  0, sizeof(float) * N_NODES, 0);

    prep_weights<<<64, 256>>>(W1l, W1r, W2l, W2r, W1c, W2c);

    // Layer 1 aggregation of raw x (+ degree count)
    {
        long long total = (long long)N_EDGES * 32;
        scatter_kernel<32, 32, true><<<(unsigned)((total + 255) / 256), 256>>>(
            x, ei, agg1, cnt);
    }

    // h = relu([agg1/cnt | x] @ [W1_l; W1_r] + b1)
    sgemm_k<16, true, true><<<782, 256>>>(agg1, x, cnt, W1c, b1, h);

    // t2 = h @ [W2_l | W2_r]
    sgemm_k<8, false, false><<<782, 256>>>(h, nullptr, nullptr, W2c, nullptr, t2);

    // Layer 2 aggregation of the 64-d transformed features (t2 first half)
    {
        long long total = (long long)N_EDGES * 16;
        scatter_kernel<32, 16, false><<<(unsigned)((total + 255) / 256), 256>>>(
            t2, ei, agg2, nullptr);
    }

    // out = agg2/cnt + t2[:,64:] + b2
    finalize_kernel<<<(N_NODES * 16 + 255) / 256, 256>>>(agg2, t2, cnt, b2, out);
}

// round 4
// speedup vs baseline: 1.3138x; 1.3138x over previous
#include <cuda_runtime.h>
#include <cstdint>

#define N_NODES 100000
#define N_EDGES 640000
#define IN_CH 128
#define HID 128
#define OUT_CH 64

// ---------------- scratch (device globals; no allocation allowed) ----------
__device__ int   g_deg[N_NODES];
__device__ int   g_offs[N_NODES + 1];
__device__ int   g_cursor[N_NODES];
__device__ int   g_csr[N_EDGES];                  // src ids grouped by dst
__device__ float g_mean1[N_NODES * IN_CH];        // mean of x[src] at dst
__device__ float g_t2[N_NODES * (2 * OUT_CH)];    // [h@W2_l | h@W2_r]
__device__ float g_mean2[N_NODES * OUT_CH];       // mean of t2[src,0:64] at dst
__device__ float g_W1[2 * IN_CH * HID];           // [W1_l; W1_r]  (256 x 128)
__device__ float g_W2[HID * 2 * OUT_CH];          // [W2_l | W2_r] (128 x 128)

__device__ __forceinline__ int clampN(int v) {
    return min(max(v, 0), N_NODES - 1);
}

// ---------------- weight concatenation ------------------------------------
__global__ void prep_weights(const float* __restrict__ W1l,
                             const float* __restrict__ W1r,
                             const float* __restrict__ W2l,
                             const float* __restrict__ W2r,
                             float* __restrict__ W1c,
                             float* __restrict__ W2c) {
    int t = blockIdx.x * blockDim.x + threadIdx.x;   // 0 .. 16383
    if (t < IN_CH * HID) {
        W1c[t] = W1l[t];
        W1c[IN_CH * HID + t] = W1r[t];
    }
    if (t < HID * 2 * OUT_CH) {
        int k = t >> 7;
        int n = t & 127;
        W2c[t] = (n < OUT_CH) ? W2l[k * OUT_CH + n]
                              : W2r[k * OUT_CH + (n - OUT_CH)];
    }
}

// ---------------- CSR build -------------------------------------------------
__global__ void hist_kernel(const int* __restrict__ ei, int* __restrict__ deg) {
    int e = blockIdx.x * blockDim.x + threadIdx.x;
    if (e >= N_EDGES) return;
    atomicAdd(&deg[clampN(ei[N_EDGES + e])], 1);
}

// single block, 1024 threads; chunk = 98 contiguous elements per thread
__global__ void scan_kernel(const int* __restrict__ deg, int* __restrict__ offs) {
    __shared__ int part[1024];
    const int t = threadIdx.x;
    const int beg = t * 98;
    const int end = min(beg + 98, N_NODES);
    int s = 0;
    for (int i = beg; i < end; i++) s += deg[i];
    part[t] = s;
    __syncthreads();
    for (int d = 1; d < 1024; d <<= 1) {
        int v = (t >= d) ? part[t - d] : 0;
        __syncthreads();
        part[t] += v;
        __syncthreads();
    }
    int run = (t == 0) ? 0 : part[t - 1];   // exclusive prefix of this chunk
    for (int i = beg; i < end; i++) { offs[i] = run; run += deg[i]; }
    if (end == N_NODES) offs[N_NODES] = run;
}

__global__ void fill_kernel(const int* __restrict__ ei,
                            int* __restrict__ cursor,
                            int* __restrict__ csr) {
    int e = blockIdx.x * blockDim.x + threadIdx.x;
    if (e >= N_EDGES) return;
    int s = clampN(ei[e]);
    int d = clampN(ei[N_EDGES + e]);
    int pos = atomicAdd(&cursor[d], 1);
    csr[pos] = s;
}

// ---------------- gather-mean aggregation (no atomics) ----------------------
// Layer 1: one warp per node, each lane owns one float4 of the 128-d row.
__global__ void aggregate1(const float* __restrict__ x,
                           const int* __restrict__ csr,
                           const int* __restrict__ offs,
                           float* __restrict__ mean1) {
    int n = blockIdx.x * (blockDim.x >> 5) + (threadIdx.x >> 5);
    if (n >= N_NODES) return;
    int lane = threadIdx.x & 31;
    int beg = offs[n], end = offs[n + 1];
    float4 acc = make_float4(0.f, 0.f, 0.f, 0.f);
    for (int p = beg; p < end; ++p) {
        int s = csr[p];
        float4 v = ((const float4*)x)[(long long)s * 32 + lane];
        acc.x += v.x; acc.y += v.y; acc.z += v.z; acc.w += v.w;
    }
    int deg = end - beg;
    float inv = deg > 0 ? 1.f / (float)deg : 0.f;
    acc.x *= inv; acc.y *= inv; acc.z *= inv; acc.w *= inv;
    ((float4*)mean1)[(long long)n * 32 + lane] = acc;
}

// Layer 2: one warp per node over 64-d rows (t2 left half); two edges per step.
__global__ void aggregate2(const float* __restrict__ t2,
                           const int* __restrict__ csr,
                           const int* __restrict__ offs,
                           float* __restrict__ mean2) {
    int n = blockIdx.x * (blockDim.x >> 5) + (threadIdx.x >> 5);
    if (n >= N_NODES) return;
    int lane = threadIdx.x & 31;
    int half = lane >> 4;          // 0 or 1
    int j    = lane & 15;          // float4 index within 64-d row
    int beg = offs[n], end = offs[n + 1];
    float4 acc = make_float4(0.f, 0.f, 0.f, 0.f);
    for (int p = beg + half; p < end; p += 2) {
        int s = csr[p];
        float4 v = ((const float4*)t2)[(long long)s * 32 + j];
        acc.x += v.x; acc.y += v.y; acc.z += v.z; acc.w += v.w;
    }
    acc.x += __shfl_xor_sync(0xffffffffu, acc.x, 16);
    acc.y += __shfl_xor_sync(0xffffffffu, acc.y, 16);
    acc.z += __shfl_xor_sync(0xffffffffu, acc.z, 16);
    acc.w += __shfl_xor_sync(0xffffffffu, acc.w, 16);
    if (half == 0) {
        int deg = end - beg;
        float inv = deg > 0 ? 1.f / (float)deg : 0.f;
        acc.x *= inv; acc.y *= inv; acc.z *= inv; acc.w *= inv;
        ((float4*)mean2)[(long long)n * 16 + j] = acc;
    }
}

// ---------------- fused GEMM: h = relu([mean1|x]@W1c + b1); t2 = h@W2c ------
// BM=128, BN=128, BK=16; 256 threads, 8x8 microtile. h stays in smem.
// dynamic smem layout: As[16][128] | Bs[16][128] | Hs[128][132]
__global__ void __launch_bounds__(256, 2)
fused_gemm(const float* __restrict__ A0,   // mean1
           const float* __restrict__ A1,   // x
           const float* __restrict__ W1c,
           const float* __restrict__ b1,
           const float* __restrict__ W2c,
           float* __restrict__ t2) {
    extern __shared__ float sm[];
    float* As = sm;              // 2048 floats
    float* Bs = sm + 2048;       // 2048 floats
    float* Hs = sm + 4096;       // 128*132 floats

    const int tid = threadIdx.x;
    const int r   = tid >> 1;           // 0..127
    const int cc  = (tid & 1) << 3;     // 0 or 8
    const long long gr = (long long)blockIdx.x * 128 + r;
    const bool rowok = gr < N_NODES;

    const int ty = tid >> 4;            // 0..15
    const int tx = tid & 15;            // 0..15

    float acc[8][8];
#pragma unroll
    for (int i = 0; i < 8; i++)
#pragma unroll
        for (int j = 0; j < 8; j++) acc[i][j] = 0.f;

    // ---- phase 1: K = 256 over [mean1 | x] ----
    for (int kt = 0; kt < 16; ++kt) {
        const float* Asrc = (kt < 8) ? A0 : A1;
        int kcol = (kt & 7) * 16;
        float4 a0 = make_float4(0.f, 0.f, 0.f, 0.f), a1 = a0;
        if (rowok) {
            const float* p = Asrc + gr * 128 + kcol + cc;
            a0 = *(const float4*)p;
            a1 = *(const float4*)(p + 4);
        }
        As[(cc + 0) * 128 + r] = a0.x; As[(cc + 1) * 128 + r] = a0.y;
        As[(cc + 2) * 128 + r] = a0.z; As[(cc + 3) * 128 + r] = a0.w;
        As[(cc + 4) * 128 + r] = a1.x; As[(cc + 5) * 128 + r] = a1.y;
        As[(cc + 6) * 128 + r] = a1.z; As[(cc + 7) * 128 + r] = a1.w;
        {
            const float4* Bp = (const float4*)(W1c + (long long)kt * 16 * 128);
            float4* Bs4 = (float4*)Bs;
            Bs4[tid]       = Bp[tid];
            Bs4[tid + 256] = Bp[tid + 256];
        }
        __syncthreads();
#pragma unroll
        for (int k = 0; k < 16; k++) {
            float4 av0 = *(const float4*)&As[k * 128 + ty * 8];
            float4 av1 = *(const float4*)&As[k * 128 + ty * 8 + 4];
            float4 bv0 = *(const float4*)&Bs[k * 128 + tx * 8];
            float4 bv1 = *(const float4*)&Bs[k * 128 + tx * 8 + 4];
            float a[8] = {av0.x, av0.y, av0.z, av0.w, av1.x, av1.y, av1.z, av1.w};
            float b[8] = {bv0.x, bv0.y, bv0.z, bv0.w, bv1.x, bv1.y, bv1.z, bv1.w};
#pragma unroll
            for (int i = 0; i < 8; i++)
#pragma unroll
                for (int j = 0; j < 8; j++)
                    acc[i][j] = fmaf(a[i], b[j], acc[i][j]);
        }
        __syncthreads();
    }

    // ---- epilogue 1: relu(+bias) -> Hs (h never leaves smem) ----
    {
        float bb[8];
#pragma unroll
        for (int j = 0; j < 8; j++) bb[j] = b1[tx * 8 + j];
#pragma unroll
        for (int i = 0; i < 8; i++) {
            float v[8];
#pragma unroll
            for (int j = 0; j < 8; j++)
                v[j] = fmaxf(acc[i][j] + bb[j], 0.f);
            float* hp = &Hs[(ty * 8 + i) * 132 + tx * 8];
            *(float4*)hp       = make_float4(v[0], v[1], v[2], v[3]);
            *(float4*)(hp + 4) = make_float4(v[4], v[5], v[6], v[7]);
        }
    }
#pragma unroll
    for (int i = 0; i < 8; i++)
#pragma unroll
        for (int j = 0; j < 8; j++) acc[i][j] = 0.f;
    __syncthreads();

    // ---- phase 2: t2_tile = Hs @ W2c  (K = 128) ----
    for (int kt = 0; kt < 8; ++kt) {
        {
            const float4* Bp = (const float4*)(W2c + (long long)kt * 16 * 128);
            float4* Bs4 = (float4*)Bs;
            Bs4[tid]       = Bp[tid];
            Bs4[tid + 256] = Bp[tid + 256];
        }
        __syncthreads();
#pragma unroll
        for (int k = 0; k < 16; k++) {
            int kk = kt * 16 + k;
            float a[8];
#pragma unroll
            for (int i = 0; i < 8; i++) a[i] = Hs[(ty * 8 + i) * 132 + kk];
            float4 bv0 = *(const float4*)&Bs[k * 128 + tx * 8];
            float4 bv1 = *(const float4*)&Bs[k * 128 + tx * 8 + 4];
            float b[8] = {bv0.x, bv0.y, bv0.z, bv0.w, bv1.x, bv1.y, bv1.z, bv1.w};
#pragma unroll
            for (int i = 0; i < 8; i++)
#pragma unroll
                for (int j = 0; j < 8; j++)
                    acc[i][j] = fmaf(a[i], b[j], acc[i][j]);
        }
        __syncthreads();
    }

    // ---- epilogue 2: write t2 ----
#pragma unroll
    for (int i = 0; i < 8; i++) {
        long long row = (long long)blockIdx.x * 128 + ty * 8 + i;
        if (row >= N_NODES) continue;
        float* cp = t2 + row * 128 + tx * 8;
        *(float4*)cp       = make_float4(acc[i][0], acc[i][1], acc[i][2], acc[i][3]);
        *(float4*)(cp + 4) = make_float4(acc[i][4], acc[i][5], acc[i][6], acc[i][7]);
    }
}

// ---------------- finalize: out = mean2 + t2[:,64:] + b2 --------------------
__global__ void finalize_kernel(const float* __restrict__ mean2,
                                const float* __restrict__ t2,
                                const float* __restrict__ b2,
                                float* __restrict__ out) {
    int t = blockIdx.x * blockDim.x + threadIdx.x;   // per float4
    if (t >= N_NODES * 16) return;
    int i = t >> 4;
    int j = t & 15;
    float4 a  = ((const float4*)mean2)[t];
    float4 tv = ((const float4*)t2)[(long long)i * 32 + 16 + j];
    float4 b  = ((const float4*)b2)[j];
    float4 o;
    o.x = a.x + tv.x + b.x;
    o.y = a.y + tv.y + b.y;
    o.z = a.z + tv.z + b.z;
    o.w = a.w + tv.w + b.w;
    ((float4*)out)[t] = o;
}

// ---------------- launch ----------------------------------------------------
extern "C" void kernel_launch(void* const* d_in, const int* in_sizes, int n_in,
                              void* d_out, int out_size) {
    const float* x   = (const float*)d_in[0];
    const int*   ei  = (const int*)d_in[1];
    const float* W1l = (const float*)d_in[2];
    const float* W1r = (const float*)d_in[3];
    const float* b1  = (const float*)d_in[4];
    const float* W2l = (const float*)d_in[5];
    const float* W2r = (const float*)d_in[6];
    const float* b2  = (const float*)d_in[7];
    float* out = (float*)d_out;

    int *deg, *offs, *cursor, *csr;
    float *mean1, *t2, *mean2, *W1c, *W2c;
    cudaGetSymbolAddress((void**)&deg,    g_deg);
    cudaGetSymbolAddress((void**)&offs,   g_offs);
    cudaGetSymbolAddress((void**)&cursor, g_cursor);
    cudaGetSymbolAddress((void**)&csr,    g_csr);
    cudaGetSymbolAddress((void**)&mean1,  g_mean1);
    cudaGetSymbolAddress((void**)&t2,     g_t2);
    cudaGetSymbolAddress((void**)&mean2,  g_mean2);
    cudaGetSymbolAddress((void**)&W1c,    g_W1);
    cudaGetSymbolAddress((void**)&W2c,    g_W2);

    static bool attr_set = false;
    if (!attr_set) {
        cudaFuncSetAttribute(fused_gemm,
                             cudaFuncAttributeMaxDynamicSharedMemorySize,
                             (4096 + 128 * 132) * sizeof(float));
        attr_set = true;
    }

    cudaMemsetAsync(deg, 0, sizeof(int) * N_NODES, 0);

    prep_weights<<<64, 256>>>(W1l, W1r, W2l, W2r, W1c, W2c);

    // CSR build
    hist_kernel<<<(N_EDGES + 255) / 256, 256>>>(ei, deg);
    scan_kernel<<<1, 1024>>>(deg, offs);
    cudaMemcpyAsync(cursor, offs, sizeof(int) * N_NODES,
                    cudaMemcpyDeviceToDevice, 0);
    fill_kernel<<<(N_EDGES + 255) / 256, 256>>>(ei, cursor, csr);

    // Layer 1 mean aggregation (gather, no atomics)
    aggregate1<<<(N_NODES * 32 + 255) / 256, 256>>>(x, csr, offs, mean1);

    // h = relu([mean1|x]@W1c + b1) ; t2 = h@[W2_l|W2_r]   (h stays in smem)
    fused_gemm<<<782, 256, (4096 + 128 * 132) * sizeof(float)>>>(
        mean1, x, W1c, b1, W2c, t2);

    // Layer 2 mean aggregation over t2 left half
    aggregate2<<<(N_NODES * 32 + 255) / 256, 256>>>(t2, csr, offs, mean2);

    // out = mean2 + t2[:,64:] + b2
    finalize_kernel<<<(N_NODES * 16 + 255) / 256, 256>>>(mean2, t2, b2, out);
}